// round 10
// baseline (speedup 1.0000x reference)
#include <cuda_runtime.h>
#include <cuda_fp16.h>
#include <cstdint>

// out[b,d,k] = sum_e S[k,d,e] * (x[b,e,k] - mu[e,k])
// B=8192, D=E=64, K=128. fp32 in/out.
// R10: R9 was L1-latency-limited (L1 65%, issue 10%). Double warps: 512
// threads x 2 CTAs/SM = 32 warps/SM. Warp tile 2k x 16b x 32d (D = 32 regs)
// to fit the 64-reg/thread budget (launch_bounds(512,2)). mu via smem tile.

#define NBY 18

static constexpr int AOFF   = 0;        // 8 x 4KB A tiles; doubles as Dbuf (32KB)
static constexpr int BOFF   = 32768;    // 8 x 8KB B tiles (64KB)
static constexpr int MUOFF  = 98304;    // 2KB mu tile
static constexpr int SMEM_BYTES = 100352;

__device__ __forceinline__ uint32_t cvt2(float hi, float lo) {
    uint32_t r;
    asm("cvt.rn.f16x2.f32 %0, %1, %2;" : "=r"(r) : "f"(hi), "f"(lo));
    return r;
}
__device__ __forceinline__ void ldm_x4(uint32_t& r0, uint32_t& r1, uint32_t& r2,
                                       uint32_t& r3, uint32_t addr) {
    asm volatile("ldmatrix.sync.aligned.m8n8.x4.shared.b16 {%0,%1,%2,%3}, [%4];"
                 : "=r"(r0), "=r"(r1), "=r"(r2), "=r"(r3) : "r"(addr));
}
__device__ __forceinline__ void ldm_x4t(uint32_t& r0, uint32_t& r1, uint32_t& r2,
                                        uint32_t& r3, uint32_t addr) {
    asm volatile("ldmatrix.sync.aligned.m8n8.x4.trans.shared.b16 {%0,%1,%2,%3}, [%4];"
                 : "=r"(r0), "=r"(r1), "=r"(r2), "=r"(r3) : "r"(addr));
}
__device__ __forceinline__ void mma16816(float& d0, float& d1, float& d2, float& d3,
                                         uint32_t a0, uint32_t a1, uint32_t a2, uint32_t a3,
                                         uint32_t b0, uint32_t b1) {
    asm volatile(
        "mma.sync.aligned.m16n8k16.row.col.f32.f16.f16.f32 "
        "{%0,%1,%2,%3}, {%4,%5,%6,%7}, {%8,%9}, {%0,%1,%2,%3};"
        : "+f"(d0), "+f"(d1), "+f"(d2), "+f"(d3)
        : "r"(a0), "r"(a1), "r"(a2), "r"(a3), "r"(b0), "r"(b1));
}

__global__ __launch_bounds__(512, 2)
void cluster_norm_mma_kernel(const float* __restrict__ x,
                             const float* __restrict__ mu,
                             const float* __restrict__ S,
                             float* __restrict__ out)
{
    extern __shared__ char smem[];
    const uint32_t sb = (uint32_t)__cvta_generic_to_shared(smem);
    const int tid   = threadIdx.x;
    const int lane  = tid & 31;
    const int w     = tid >> 5;
    const int kbase = blockIdx.x * 8;

    // ---- mu tile: Mu[ep][kh][8 floats]: e-pair major (matches phase-1) ----
    // layout: float idx = ep*16 + kh*8 : {e=2ep k 4..}, but store as
    // Mu[e][k 0..7]: float idx = e*8 + k. (2KB)
    if (tid < 128) {
        int e = tid >> 1, h = tid & 1;
        float4 v = *(const float4*)(mu + (size_t)e * 128 + kbase + h * 4);
        *(float4*)(smem + MUOFF + e * 32 + h * 16) = v;
    }

    // ---- S -> fp16 B tiles: Bk[e][d], rows 128B, slot ^= (e&7) ----
    #pragma unroll 4
    for (int i = 0; i < 32; i++) {
        int o  = tid + 512 * i;
        int e  = o & 63;
        int dp = (o >> 6) & 31;
        int k  = o >> 11;
        const float* sp = S + (size_t)(kbase + k) * 4096 + (size_t)(dp * 2) * 64 + e;
        float s0 = sp[0];
        float s1 = sp[64];
        uint32_t h2 = cvt2(s1, s0);   // lo = even d
        uint32_t a = sb + BOFF + k * 8192 + e * 128
                   + ((((uint32_t)(dp >> 2)) ^ (uint32_t)(e & 7)) << 4) + (dp & 3) * 4;
        asm volatile("st.shared.b32 [%0], %1;" :: "r"(a), "r"(h2) : "memory");
    }
    __syncthreads();

    // ---- thread's fixed (kh, ep) for phase 1 ----
    const int kh    = tid & 1;
    const int ep    = (tid >> 1) & 31;
    const int bbase = tid >> 6;          // 0..7

    // warp tile: kq = w&3 (2 k), bq = (w>>2)&1 (16 b), dh = w>>3 (32 d)
    const int kq  = w & 3;
    const int bq  = (w >> 2) & 1;
    const int dh  = w >> 3;
    const int l15 = lane & 15;
    const int lhi = lane >> 4;
    const int rA  = bq * 16 + l15;
    const int g   = lane >> 2;
    const int tg  = lane & 3;

    for (int bt = blockIdx.y; bt < 256; bt += NBY) {
        const int b0 = bt * 32;

        // ======= Phase 1: x - mu -> fp16 A tiles =======
        // 2048 tasks = 32 b x 32 ep x 2 kh; thread: fixed (kh,ep), b = bbase+8i.
        #pragma unroll
        for (int i = 0; i < 4; i++) {
            const int b = bbase + 8 * i;
            const float* xp = x + (size_t)(b0 + b) * 8192 + (size_t)(2 * ep) * 128
                            + kbase + kh * 4;
            float4 xa = *(const float4*)(xp);        // e = 2ep,   k kh*4..+3
            float4 xb = *(const float4*)(xp + 128);  // e = 2ep+1
            const float* mp = (const float*)(smem + MUOFF);
            float4 ma = *(const float4*)(mp + (2 * ep) * 8 + kh * 4);
            float4 mb = *(const float4*)(mp + (2 * ep + 1) * 8 + kh * 4);
            float va[4], vb[4];
            va[0] = xa.x - ma.x; va[1] = xa.y - ma.y;
            va[2] = xa.z - ma.z; va[3] = xa.w - ma.w;
            vb[0] = xb.x - mb.x; vb[1] = xb.y - mb.y;
            vb[2] = xb.z - mb.z; vb[3] = xb.w - mb.w;
            uint32_t base = sb + AOFF + b * 128
                          + ((((uint32_t)(ep >> 2)) ^ (uint32_t)(b & 7)) << 4)
                          + (ep & 3) * 4;
            #pragma unroll
            for (int j = 0; j < 4; j++) {
                uint32_t h2 = cvt2(vb[j], va[j]);    // lo = even e
                asm volatile("st.shared.b32 [%0], %1;"
                             :: "r"(base + (uint32_t)((kh * 4 + j) * 4096)), "r"(h2)
                             : "memory");
            }
        }
        __syncthreads();

        // ======= Phase 2: MMAs (warp: 2 k x 16 b x 32 d) =======
        float D[2][16];
        #pragma unroll
        for (int a = 0; a < 2; a++)
            #pragma unroll
            for (int j = 0; j < 16; j++) D[a][j] = 0.f;

        #pragma unroll
        for (int kk = 0; kk < 2; kk++) {
            const int k = kq * 2 + kk;
            const uint32_t Ab = sb + AOFF + k * 4096;
            const uint32_t Bb = sb + BOFF + k * 8192;
            #pragma unroll
            for (int es = 0; es < 4; es++) {
                uint32_t a0, a1, a2, a3;
                uint32_t aaddr = Ab + rA * 128
                               + ((((uint32_t)(es * 2 + lhi)) ^ (uint32_t)(rA & 7)) << 4);
                ldm_x4(a0, a1, a2, a3, aaddr);
                const int rB = es * 16 + l15;
                const uint32_t brow = Bb + rB * 128;
                #pragma unroll
                for (int ncp = 0; ncp < 2; ncp++) {
                    const int nc = dh * 4 + ncp * 2;
                    uint32_t b0r, b1r, b2r, b3r;
                    uint32_t baddr = brow
                        + ((((uint32_t)(nc + lhi)) ^ (uint32_t)(rB & 7)) << 4);
                    ldm_x4t(b0r, b1r, b2r, b3r, baddr);
                    mma16816(D[kk][ncp*8+0], D[kk][ncp*8+1], D[kk][ncp*8+2], D[kk][ncp*8+3],
                             a0, a1, a2, a3, b0r, b1r);
                    mma16816(D[kk][ncp*8+4], D[kk][ncp*8+5], D[kk][ncp*8+6], D[kk][ncp*8+7],
                             a0, a1, a2, a3, b2r, b3r);
                }
            }
        }
        __syncthreads();   // all mma reads of A done before Dbuf overwrites it

        // ======= Phase 3+4: two 32-d passes through Dbuf (= A region) =======
        // Dbuf row dl (0..31) x 1024B; slot16 = (bb*2 + (kq>>1)) ^ (dl&7),
        // 8B sub-slot = kq&1. Thread stores its 2 kk (contiguous k) as v2.
        #pragma unroll
        for (int p = 0; p < 2; p++) {
            if (dh == p) {
                #pragma unroll
                for (int ncl = 0; ncl < 4; ncl++) {
                    #pragma unroll
                    for (int j = 0; j < 4; j++) {
                        const int bb = bq * 16 + g + ((j & 2) ? 8 : 0);
                        const int dl = ncl * 8 + tg * 2 + (j & 1);
                        const uint32_t slot = (uint32_t)(bb * 2 + (kq >> 1)) ^ (uint32_t)(dl & 7);
                        const uint32_t addr = sb + (uint32_t)(dl * 1024) + (slot << 4)
                                            + (uint32_t)((kq & 1) * 8);
                        asm volatile("st.shared.v2.f32 [%0], {%1,%2};"
                                     :: "r"(addr),
                                        "f"(D[0][ncl*4+j]), "f"(D[1][ncl*4+j]) : "memory");
                    }
                }
            }
            __syncthreads();

            // coalesced store: o: kh2 = o&1, dl = (o>>1)&31, bb = (o>>6)&31
            #pragma unroll
            for (int i = 0; i < 4; i++) {
                int o   = tid + 512 * i;
                int kh2 = o & 1;
                int dl  = (o >> 1) & 31;
                int bb  = (o >> 6) & 31;
                uint32_t slot = (uint32_t)(bb * 2 + kh2) ^ (uint32_t)(dl & 7);
                float4 f;
                asm volatile("ld.shared.v4.f32 {%0,%1,%2,%3}, [%4];"
                             : "=f"(f.x), "=f"(f.y), "=f"(f.z), "=f"(f.w)
                             : "r"(sb + (uint32_t)(dl * 1024) + (slot << 4)));
                float* op = out + (size_t)(b0 + bb) * 8192
                          + (size_t)(p * 32 + dl) * 128 + kbase + kh2 * 4;
                *(float4*)(op) = f;
            }
            __syncthreads();
        }
    }
}

extern "C" void kernel_launch(void* const* d_in, const int* in_sizes, int n_in,
                              void* d_out, int out_size)
{
    const float* x  = (const float*)d_in[0];   // [8192, 64, 128]
    const float* mu = (const float*)d_in[1];   // [64, 128]
    const float* S  = (const float*)d_in[2];   // [128, 64, 64]
    float* out      = (float*)d_out;           // [8192, 64, 128]

    cudaFuncSetAttribute(cluster_norm_mma_kernel,
                         cudaFuncAttributeMaxDynamicSharedMemorySize, SMEM_BYTES);

    dim3 grid(16, NBY);
    cluster_norm_mma_kernel<<<grid, 512, SMEM_BYTES>>>(x, mu, S, out);
}

// round 11
// speedup vs baseline: 1.5213x; 1.5213x over previous
#include <cuda_runtime.h>
#include <cuda_fp16.h>
#include <cstdint>

// out[b,d,k] = sum_e S[k,d,e] * (x[b,e,k] - mu[e,k])
// B=8192, D=E=64, K=128. fp32 in/out.
// R11: KT=16 (64B k-granules) halves LDG/STG/Dbuf wavefronts per output.
// CTA = 16k x 32b, 512 threads, 16 warps = 4kq x 2bq x 2dh (R9 warp shape).
// A tiles stride-padded (4112) to fix kq bank aliasing; Dbuf reuses A region
// in two 32-d passes with a bank-balanced slot swizzle.

#define NBY  18
#define ASTR 4112

static constexpr int AOFF = 0;                    // 16 A tiles (65792 B); Dbuf reuse (64KB)
static constexpr int BOFF = 65792;                // 16 x 8192 B tiles (131072 B)
static constexpr int SMEM_BYTES = 65792 + 131072; // 196864

__device__ __forceinline__ uint32_t cvt2(float hi, float lo) {
    uint32_t r;
    asm("cvt.rn.f16x2.f32 %0, %1, %2;" : "=r"(r) : "f"(hi), "f"(lo));
    return r;
}
__device__ __forceinline__ void ldm_x4(uint32_t& r0, uint32_t& r1, uint32_t& r2,
                                       uint32_t& r3, uint32_t addr) {
    asm volatile("ldmatrix.sync.aligned.m8n8.x4.shared.b16 {%0,%1,%2,%3}, [%4];"
                 : "=r"(r0), "=r"(r1), "=r"(r2), "=r"(r3) : "r"(addr));
}
__device__ __forceinline__ void ldm_x4t(uint32_t& r0, uint32_t& r1, uint32_t& r2,
                                        uint32_t& r3, uint32_t addr) {
    asm volatile("ldmatrix.sync.aligned.m8n8.x4.trans.shared.b16 {%0,%1,%2,%3}, [%4];"
                 : "=r"(r0), "=r"(r1), "=r"(r2), "=r"(r3) : "r"(addr));
}
__device__ __forceinline__ void mma16816(float& d0, float& d1, float& d2, float& d3,
                                         uint32_t a0, uint32_t a1, uint32_t a2, uint32_t a3,
                                         uint32_t b0, uint32_t b1) {
    asm volatile(
        "mma.sync.aligned.m16n8k16.row.col.f32.f16.f16.f32 "
        "{%0,%1,%2,%3}, {%4,%5,%6,%7}, {%8,%9}, {%0,%1,%2,%3};"
        : "+f"(d0), "+f"(d1), "+f"(d2), "+f"(d3)
        : "r"(a0), "r"(a1), "r"(a2), "r"(a3), "r"(b0), "r"(b1));
}

__global__ __launch_bounds__(512, 1)
void cluster_norm_mma_kernel(const float* __restrict__ x,
                             const float* __restrict__ mu,
                             const float* __restrict__ S,
                             float* __restrict__ out)
{
    extern __shared__ char smem[];
    const uint32_t sb = (uint32_t)__cvta_generic_to_shared(smem);
    const int tid   = threadIdx.x;
    const int lane  = tid & 31;
    const int w     = tid >> 5;
    const int kbase = blockIdx.x * 16;

    // ---- S -> fp16 B tiles: Bk[e][d], rows 128B, slot ^= (e&7) ----
    #pragma unroll 4
    for (int i = 0; i < 64; i++) {
        int o  = tid + 512 * i;
        int e  = o & 63;
        int dp = (o >> 6) & 31;
        int k  = o >> 11;                 // 0..15
        const float* sp = S + (size_t)(kbase + k) * 4096 + (size_t)(dp * 2) * 64 + e;
        float s0 = sp[0];
        float s1 = sp[64];
        uint32_t h2 = cvt2(s1, s0);       // lo = even d
        uint32_t a = sb + BOFF + k * 8192 + e * 128
                   + ((((uint32_t)(dp >> 2)) ^ (uint32_t)(e & 7)) << 4) + (dp & 3) * 4;
        asm volatile("st.shared.b32 [%0], %1;" :: "r"(a), "r"(h2) : "memory");
    }

    // ---- phase-1 thread constants + mu register preload ----
    // kq1 = tid&3 (k-quad), ep = (tid>>2)&31 (e-pair), bbase = tid>>7 (0..3)
    const int kq1   = tid & 3;
    const int ep    = (tid >> 2) & 31;
    const int bbase = tid >> 7;
    float4 m0 = *(const float4*)(mu + (size_t)(2 * ep) * 128 + kbase + kq1 * 4);
    float4 m1 = *(const float4*)(mu + (size_t)(2 * ep + 1) * 128 + kbase + kq1 * 4);
    __syncthreads();

    // warp tile: kq = w&3 (4 k), bq = (w>>2)&1 (16 b), dh = w>>3 (32 d)
    const int kq  = w & 3;
    const int bq  = (w >> 2) & 1;
    const int dh  = w >> 3;
    const int l15 = lane & 15;
    const int lhi = lane >> 4;
    const int rA  = bq * 16 + l15;
    const int g   = lane >> 2;
    const int tg  = lane & 3;

    for (int bt = blockIdx.y; bt < 256; bt += NBY) {
        const int b0 = bt * 32;

        // ======= Phase 1: x - mu -> fp16 A tiles =======
        // 4096 tasks = 32 b x 32 ep x 4 kq1; thread: fixed (kq1,ep), b = bbase+4i.
        #pragma unroll
        for (int i = 0; i < 8; i++) {
            const int b = bbase + 4 * i;
            const float* xp = x + (size_t)(b0 + b) * 8192 + (size_t)(2 * ep) * 128
                            + kbase + kq1 * 4;
            float4 xa = *(const float4*)(xp);        // e = 2ep,   k = 4kq1..+3
            float4 xb = *(const float4*)(xp + 128);  // e = 2ep+1
            float va[4], vb[4];
            va[0] = xa.x - m0.x; va[1] = xa.y - m0.y;
            va[2] = xa.z - m0.z; va[3] = xa.w - m0.w;
            vb[0] = xb.x - m1.x; vb[1] = xb.y - m1.y;
            vb[2] = xb.z - m1.z; vb[3] = xb.w - m1.w;
            uint32_t base = sb + AOFF + (uint32_t)(kq1 * 4) * ASTR + b * 128
                          + ((((uint32_t)(ep >> 2)) ^ (uint32_t)(b & 7)) << 4)
                          + (ep & 3) * 4;
            #pragma unroll
            for (int j = 0; j < 4; j++) {
                uint32_t h2 = cvt2(vb[j], va[j]);    // lo = even e
                asm volatile("st.shared.b32 [%0], %1;"
                             :: "r"(base + (uint32_t)(j * ASTR)), "r"(h2) : "memory");
            }
        }
        __syncthreads();

        // ======= Phase 2: MMAs (warp: 4 k x 16 b x 32 d) =======
        float D[4][16];
        #pragma unroll
        for (int a = 0; a < 4; a++)
            #pragma unroll
            for (int j = 0; j < 16; j++) D[a][j] = 0.f;

        #pragma unroll
        for (int kk = 0; kk < 4; kk++) {
            const int k = kq * 4 + kk;
            const uint32_t Ab = sb + AOFF + (uint32_t)k * ASTR;
            const uint32_t Bb = sb + BOFF + (uint32_t)k * 8192;
            #pragma unroll
            for (int es = 0; es < 4; es++) {
                uint32_t a0, a1, a2, a3;
                uint32_t aaddr = Ab + rA * 128
                               + ((((uint32_t)(es * 2 + lhi)) ^ (uint32_t)(rA & 7)) << 4);
                ldm_x4(a0, a1, a2, a3, aaddr);
                const int rB = es * 16 + l15;
                const uint32_t brow = Bb + rB * 128;
                #pragma unroll
                for (int ncp = 0; ncp < 2; ncp++) {
                    const int nc = dh * 4 + ncp * 2;
                    uint32_t b0r, b1r, b2r, b3r;
                    uint32_t baddr = brow
                        + ((((uint32_t)(nc + lhi)) ^ (uint32_t)(rB & 7)) << 4);
                    ldm_x4t(b0r, b1r, b2r, b3r, baddr);
                    mma16816(D[kk][ncp*8+0], D[kk][ncp*8+1], D[kk][ncp*8+2], D[kk][ncp*8+3],
                             a0, a1, a2, a3, b0r, b1r);
                    mma16816(D[kk][ncp*8+4], D[kk][ncp*8+5], D[kk][ncp*8+6], D[kk][ncp*8+7],
                             a0, a1, a2, a3, b2r, b3r);
                }
            }
        }
        __syncthreads();   // all mma reads of A done before Dbuf overwrites it

        // ======= Phase 3+4: two 32-d passes through Dbuf (= A region) =======
        // Dbuf: row dl (0..31) x 2048B = 32 bb x 64B (16 k).
        // slot16 = (bb*4 + kq) ^ (dl&7) ^ ((bb>>1)&1)  (bank-balanced: 4 wf)
        #pragma unroll
        for (int p = 0; p < 2; p++) {
            if (dh == p) {
                #pragma unroll
                for (int ncl = 0; ncl < 4; ncl++) {
                    #pragma unroll
                    for (int j = 0; j < 4; j++) {
                        const int bb = bq * 16 + g + ((j & 2) ? 8 : 0);
                        const int dl = ncl * 8 + tg * 2 + (j & 1);
                        const uint32_t slot = ((uint32_t)(bb * 4 + kq))
                                            ^ (uint32_t)(dl & 7) ^ (uint32_t)((bb >> 1) & 1);
                        const uint32_t addr = sb + (uint32_t)(dl * 2048) + (slot << 4);
                        asm volatile("st.shared.v4.f32 [%0], {%1,%2,%3,%4};"
                                     :: "r"(addr),
                                        "f"(D[0][ncl*4+j]), "f"(D[1][ncl*4+j]),
                                        "f"(D[2][ncl*4+j]), "f"(D[3][ncl*4+j]) : "memory");
                    }
                }
            }
            __syncthreads();

            // coalesced store: o: kq2 = o&3, dl = (o>>2)&31, bb = (o>>7)&31
            #pragma unroll
            for (int i = 0; i < 8; i++) {
                int o   = tid + 512 * i;
                int kq2 = o & 3;
                int dl  = (o >> 2) & 31;
                int bb  = (o >> 7) & 31;
                uint32_t slot = ((uint32_t)(bb * 4 + kq2))
                              ^ (uint32_t)(dl & 7) ^ (uint32_t)((bb >> 1) & 1);
                float4 f;
                asm volatile("ld.shared.v4.f32 {%0,%1,%2,%3}, [%4];"
                             : "=f"(f.x), "=f"(f.y), "=f"(f.z), "=f"(f.w)
                             : "r"(sb + (uint32_t)(dl * 2048) + (slot << 4)));
                float* op = out + (size_t)(b0 + bb) * 8192
                          + (size_t)(p * 32 + dl) * 128 + kbase + kq2 * 4;
                *(float4*)(op) = f;
            }
            __syncthreads();
        }
    }
}

extern "C" void kernel_launch(void* const* d_in, const int* in_sizes, int n_in,
                              void* d_out, int out_size)
{
    const float* x  = (const float*)d_in[0];   // [8192, 64, 128]
    const float* mu = (const float*)d_in[1];   // [64, 128]
    const float* S  = (const float*)d_in[2];   // [128, 64, 64]
    float* out      = (float*)d_out;           // [8192, 64, 128]

    cudaFuncSetAttribute(cluster_norm_mma_kernel,
                         cudaFuncAttributeMaxDynamicSharedMemorySize, SMEM_BYTES);

    dim3 grid(8, NBY);
    cluster_norm_mma_kernel<<<grid, 512, SMEM_BYTES>>>(x, mu, S, out);
}

// round 12
// speedup vs baseline: 1.7490x; 1.1497x over previous
#include <cuda_runtime.h>
#include <cuda_fp16.h>
#include <cstdint>

// out[b,d,k] = sum_e S[k,d,e] * (x[b,e,k] - mu[e,k])
// B=8192, D=E=64, K=128. fp32 in/out.
// R12: software-pipelined b-sub-tiles of 16. Per sub-tile: LDG(next) issued
// before MMA(cur) so DRAM latency hides under tensor work; convert+STS into
// the alternate A buffer; epilogue reuses the retired A buffer as Dbuf.
// KT=16 (64B k-granules), 512 threads, 16 warps = 4kq x 4dh x (16 b shared).

#define NBY  18
#define ASTR 2064                         // per-k A stride (16 rows x 128B + pad)

static constexpr int ABUF  = 16 * ASTR;   // 33024 per buffer (Dbuf needs 32768)
static constexpr int BOFF  = 2 * ABUF;    // 66048
static constexpr int SMEM_BYTES = BOFF + 16 * 8192;   // 197120

__device__ __forceinline__ uint32_t cvt2(float hi, float lo) {
    uint32_t r;
    asm("cvt.rn.f16x2.f32 %0, %1, %2;" : "=r"(r) : "f"(hi), "f"(lo));
    return r;
}
__device__ __forceinline__ void ldm_x4(uint32_t& r0, uint32_t& r1, uint32_t& r2,
                                       uint32_t& r3, uint32_t addr) {
    asm volatile("ldmatrix.sync.aligned.m8n8.x4.shared.b16 {%0,%1,%2,%3}, [%4];"
                 : "=r"(r0), "=r"(r1), "=r"(r2), "=r"(r3) : "r"(addr));
}
__device__ __forceinline__ void ldm_x4t(uint32_t& r0, uint32_t& r1, uint32_t& r2,
                                        uint32_t& r3, uint32_t addr) {
    asm volatile("ldmatrix.sync.aligned.m8n8.x4.trans.shared.b16 {%0,%1,%2,%3}, [%4];"
                 : "=r"(r0), "=r"(r1), "=r"(r2), "=r"(r3) : "r"(addr));
}
__device__ __forceinline__ void mma16816(float& d0, float& d1, float& d2, float& d3,
                                         uint32_t a0, uint32_t a1, uint32_t a2, uint32_t a3,
                                         uint32_t b0, uint32_t b1) {
    asm volatile(
        "mma.sync.aligned.m16n8k16.row.col.f32.f16.f16.f32 "
        "{%0,%1,%2,%3}, {%4,%5,%6,%7}, {%8,%9}, {%0,%1,%2,%3};"
        : "+f"(d0), "+f"(d1), "+f"(d2), "+f"(d3)
        : "r"(a0), "r"(a1), "r"(a2), "r"(a3), "r"(b0), "r"(b1));
}

__global__ __launch_bounds__(512, 1)
void cluster_norm_mma_kernel(const float* __restrict__ x,
                             const float* __restrict__ mu,
                             const float* __restrict__ S,
                             float* __restrict__ out)
{
    extern __shared__ char smem[];
    const uint32_t sb = (uint32_t)__cvta_generic_to_shared(smem);
    const int tid   = threadIdx.x;
    const int lane  = tid & 31;
    const int w     = tid >> 5;
    const int kbase = blockIdx.x * 16;
    const int by    = blockIdx.y;

    // ---- S -> fp16 B tiles: Bk[e][d], rows 128B, slot ^= (e&7) ----
    #pragma unroll 4
    for (int i = 0; i < 64; i++) {
        int o  = tid + 512 * i;
        int e  = o & 63;
        int dp = (o >> 6) & 31;
        int k  = o >> 11;                 // 0..15
        const float* sp = S + (size_t)(kbase + k) * 4096 + (size_t)(dp * 2) * 64 + e;
        float s0 = sp[0];
        float s1 = sp[64];
        uint32_t h2 = cvt2(s1, s0);       // lo = even d
        uint32_t a = sb + BOFF + k * 8192 + e * 128
                   + ((((uint32_t)(dp >> 2)) ^ (uint32_t)(e & 7)) << 4) + (dp & 3) * 4;
        asm volatile("st.shared.b32 [%0], %1;" :: "r"(a), "r"(h2) : "memory");
    }

    // ---- phase-1 thread constants + mu register preload ----
    // kq1 = tid&3 (k-quad), ep = (tid>>2)&31 (e-pair), bloc0 = tid>>7 (0..3)
    const int kq1   = tid & 3;
    const int ep    = (tid >> 2) & 31;
    const int bloc0 = tid >> 7;
    float4 m0 = *(const float4*)(mu + (size_t)(2 * ep) * 128 + kbase + kq1 * 4);
    float4 m1 = *(const float4*)(mu + (size_t)(2 * ep + 1) * 128 + kbase + kq1 * 4);

    // warp tile: kq = w&3 (4 k), dh = (w>>2)&3 (16 d), all 16 b
    const int kq  = w & 3;
    const int dh  = (w >> 2) & 3;
    const int l15 = lane & 15;
    const int lhi = lane >> 4;
    const int g   = lane >> 2;
    const int tg  = lane & 3;

    const uint32_t abase0 = sb;
    const uint32_t abase1 = sb + ABUF;

    float4 xr[4][2];

    // load sub-tile bt's x slice into registers
    auto ldx = [&](int bt) {
        const int b0 = bt * 16;
        #pragma unroll
        for (int i = 0; i < 4; i++) {
            const int b = bloc0 + 4 * i;
            const float* xp = x + (size_t)(b0 + b) * 8192 + (size_t)(2 * ep) * 128
                            + kbase + kq1 * 4;
            xr[i][0] = *(const float4*)(xp);        // e = 2ep
            xr[i][1] = *(const float4*)(xp + 128);  // e = 2ep+1
        }
    };
    // convert registers -> fp16 A tiles at abase
    auto stx = [&](uint32_t abase) {
        #pragma unroll
        for (int i = 0; i < 4; i++) {
            const int b = bloc0 + 4 * i;
            float va[4], vb[4];
            va[0] = xr[i][0].x - m0.x; va[1] = xr[i][0].y - m0.y;
            va[2] = xr[i][0].z - m0.z; va[3] = xr[i][0].w - m0.w;
            vb[0] = xr[i][1].x - m1.x; vb[1] = xr[i][1].y - m1.y;
            vb[2] = xr[i][1].z - m1.z; vb[3] = xr[i][1].w - m1.w;
            uint32_t base = abase + (uint32_t)(kq1 * 4) * ASTR + b * 128
                          + ((((uint32_t)(ep >> 2)) ^ (uint32_t)(b & 7)) << 4)
                          + (ep & 3) * 4;
            #pragma unroll
            for (int j = 0; j < 4; j++) {
                uint32_t h2 = cvt2(vb[j], va[j]);   // lo = even e
                asm volatile("st.shared.b32 [%0], %1;"
                             :: "r"(base + (uint32_t)(j * ASTR)), "r"(h2) : "memory");
            }
        }
    };

    // ---- prologue ----
    ldx(by);
    stx(abase0);
    int cur = 0;

    for (int bt = by; bt < 512; bt += NBY) {
        const int b0  = bt * 16;
        const int nxt = bt + NBY;
        const uint32_t abase = cur ? abase1 : abase0;
        const uint32_t aalt  = cur ? abase0 : abase1;

        __syncthreads();                  // A(cur) visible; prev epilogue reads done

        if (nxt < 512) ldx(nxt);          // issue global loads early (hidden by MMA)

        // ======= MMA: 4 k x 16 b x 16 d =======
        float D[4][8];
        #pragma unroll
        for (int a = 0; a < 4; a++)
            #pragma unroll
            for (int j = 0; j < 8; j++) D[a][j] = 0.f;

        #pragma unroll
        for (int kk = 0; kk < 4; kk++) {
            const int k = kq * 4 + kk;
            const uint32_t Ab = abase + (uint32_t)k * ASTR;
            const uint32_t Bb = sb + BOFF + (uint32_t)k * 8192;
            #pragma unroll
            for (int es = 0; es < 4; es++) {
                uint32_t a0, a1, a2, a3;
                uint32_t aaddr = Ab + l15 * 128
                               + ((((uint32_t)(es * 2 + lhi)) ^ (uint32_t)(l15 & 7)) << 4);
                ldm_x4(a0, a1, a2, a3, aaddr);
                const int rB = es * 16 + l15;
                uint32_t b0r, b1r, b2r, b3r;
                uint32_t baddr = sb + BOFF + (uint32_t)k * 8192 + rB * 128
                               + ((((uint32_t)(dh * 2 + lhi)) ^ (uint32_t)(rB & 7)) << 4);
                (void)Bb;
                ldm_x4t(b0r, b1r, b2r, b3r, baddr);
                mma16816(D[kk][0], D[kk][1], D[kk][2], D[kk][3],
                         a0, a1, a2, a3, b0r, b1r);
                mma16816(D[kk][4], D[kk][5], D[kk][6], D[kk][7],
                         a0, a1, a2, a3, b2r, b3r);
            }
        }

        if (nxt < 512) stx(aalt);         // stage next tile into the other buffer

        __syncthreads();                  // MMA+STS(next) done; Dbuf (= abase) free

        // ======= epilogue: two 32-d passes, Dbuf = abase region =======
        // Dbuf row dl (0..31) x 1024B; slot16 = (bb*4+kq) ^ (dl&7) ^ ((bb>>1)&1)
        #pragma unroll
        for (int p = 0; p < 2; p++) {
            if ((dh >> 1) == p) {
                const int dhl = dh & 1;
                #pragma unroll
                for (int ncl = 0; ncl < 2; ncl++) {
                    #pragma unroll
                    for (int j = 0; j < 4; j++) {
                        const int bb = g + ((j & 2) ? 8 : 0);
                        const int dl = dhl * 16 + ncl * 8 + tg * 2 + (j & 1);
                        const uint32_t slot = ((uint32_t)(bb * 4 + kq))
                                            ^ (uint32_t)(dl & 7) ^ (uint32_t)((bb >> 1) & 1);
                        const uint32_t addr = abase + (uint32_t)(dl * 1024) + (slot << 4);
                        asm volatile("st.shared.v4.f32 [%0], {%1,%2,%3,%4};"
                                     :: "r"(addr),
                                        "f"(D[0][ncl*4+j]), "f"(D[1][ncl*4+j]),
                                        "f"(D[2][ncl*4+j]), "f"(D[3][ncl*4+j]) : "memory");
                    }
                }
            }
            __syncthreads();

            // coalesced store: o: kq2 = o&3, dl = (o>>2)&31, bb = (o>>7)&15
            #pragma unroll
            for (int i = 0; i < 4; i++) {
                int o   = tid + 512 * i;
                int kq2 = o & 3;
                int dl  = (o >> 2) & 31;
                int bb  = (o >> 7) & 15;
                uint32_t slot = ((uint32_t)(bb * 4 + kq2))
                              ^ (uint32_t)(dl & 7) ^ (uint32_t)((bb >> 1) & 1);
                float4 f;
                asm volatile("ld.shared.v4.f32 {%0,%1,%2,%3}, [%4];"
                             : "=f"(f.x), "=f"(f.y), "=f"(f.z), "=f"(f.w)
                             : "r"(abase + (uint32_t)(dl * 1024) + (slot << 4)));
                float* op = out + (size_t)(b0 + bb) * 8192
                          + (size_t)(p * 32 + dl) * 128 + kbase + kq2 * 4;
                *(float4*)(op) = f;
            }
            if (p == 0) __syncthreads();  // pass-0 reads done before pass-1 writes
        }
        cur ^= 1;
        // pass-1 reads protected by next iteration's first __syncthreads()
    }
}

extern "C" void kernel_launch(void* const* d_in, const int* in_sizes, int n_in,
                              void* d_out, int out_size)
{
    const float* x  = (const float*)d_in[0];   // [8192, 64, 128]
    const float* mu = (const float*)d_in[1];   // [64, 128]
    const float* S  = (const float*)d_in[2];   // [128, 64, 64]
    float* out      = (float*)d_out;           // [8192, 64, 128]

    cudaFuncSetAttribute(cluster_norm_mma_kernel,
                         cudaFuncAttributeMaxDynamicSharedMemorySize, SMEM_BYTES);

    dim3 grid(8, NBY);
    cluster_norm_mma_kernel<<<grid, 512, SMEM_BYTES>>>(x, mu, S, out);
}